// round 2
// baseline (speedup 1.0000x reference)
#include <cuda_runtime.h>
#include <math.h>

#define S_   128
#define B_   128
#define C_   256
#define E_   256
#define D_   512
#define EMB_ 256
#define V_   10000
#define T_   32

// ---------------- scratch (static device memory; no allocation at runtime) ----
__device__ float g_pre_f[S_*B_*E_];
__device__ float g_pre_b[S_*B_*E_];
__device__ float g_enc_out[(size_t)S_*B_*2*E_];     // [s][b][0:256]=fwd, [256:512]=bwd
__device__ float g_enc_part[(size_t)S_*B_*D_];
__device__ float g_h[2][2][B_*E_];                  // [dir][buf][b*E+e]
__device__ float g_hcat[B_*2*E_];
__device__ float g_hidden[B_*D_];
__device__ float g_hW[B_*D_];
__device__ float g_x[B_*(EMB_+2*E_)];               // [emb | weighted], K=768
__device__ float g_pred_in[B_*(D_+2*E_+EMB_)];      // [h_new | weighted | emb], K=1280
__device__ float g_gi[B_*3*D_];
__device__ float g_gh[B_*3*D_];
__device__ float g_pred[B_*V_];

// packed fp32x2 FMA (sm_100a+): d = a*b + c elementwise on 2 packed floats
__device__ __forceinline__ unsigned long long ffma2(unsigned long long a,
                                                    unsigned long long b,
                                                    unsigned long long c)
{
    unsigned long long d;
    asm("fma.rn.f32x2 %0, %1, %2, %3;" : "=l"(d) : "l"(a), "l"(b), "l"(c));
    return d;
}

// ---------------- generic TN GEMM: C[M,N] = act(A[M,K] @ B[N,K]^T + bias[N]) --
// 256 threads as 16x16; thread tile TM x TN (TM even); BM=16*TM, BN=16*TN.
// Accumulators are packed f32x2 pairs along M (aligned 8B reads from As).
template<int BM, int BN, int BK, int TM, int TN, int ACT>
__global__ void gemm_tn(const float* __restrict__ A, int lda,
                        const float* __restrict__ Bm, int ldb,
                        const float* __restrict__ bias,
                        float* __restrict__ C, int ldc,
                        int M, int N, int K)
{
    __shared__ float As[BK][BM + 4];
    __shared__ float Bs[BK][BN + 4];
    const int bm = blockIdx.y * BM;
    const int bn = blockIdx.x * BN;
    const int tid = threadIdx.x;
    const int tx = tid & 15, ty = tid >> 4;
    constexpr int MP = TM / 2;

    unsigned long long acc[MP][TN];
#pragma unroll
    for (int i = 0; i < MP; i++)
#pragma unroll
        for (int j = 0; j < TN; j++) acc[i][j] = 0ull;

    for (int k0 = 0; k0 < K; k0 += BK) {
#pragma unroll
        for (int i = 0; i < (BM * BK) / 256; i++) {
            int id = tid + i * 256;
            int r = id / BK, c = id % BK;
            As[c][r] = A[(size_t)(bm + r) * lda + k0 + c];
        }
#pragma unroll
        for (int i = 0; i < (BN * BK) / 256; i++) {
            int id = tid + i * 256;
            int r = id / BK, c = id % BK;
            int n = bn + r;
            Bs[c][r] = (n < N) ? Bm[(size_t)n * ldb + k0 + c] : 0.f;
        }
        __syncthreads();
#pragma unroll
        for (int k = 0; k < BK; k++) {
            unsigned long long a2[MP], b2[TN];
#pragma unroll
            for (int i = 0; i < MP; i++)
                a2[i] = *(const unsigned long long*)&As[k][ty * TM + 2 * i];
#pragma unroll
            for (int j = 0; j < TN; j++) {
                float bv = Bs[k][tx * TN + j];
                float2 bb = make_float2(bv, bv);
                b2[j] = *(unsigned long long*)&bb;
            }
#pragma unroll
            for (int i = 0; i < MP; i++)
#pragma unroll
                for (int j = 0; j < TN; j++)
                    acc[i][j] = ffma2(a2[i], b2[j], acc[i][j]);
        }
        __syncthreads();
    }

#pragma unroll
    for (int i = 0; i < MP; i++) {
        int m0 = bm + ty * TM + 2 * i;
#pragma unroll
        for (int j = 0; j < TN; j++) {
            int n = bn + tx * TN + j;
            if (n < N) {
                float2 f = *(float2*)&acc[i][j];
                float bv = bias ? bias[n] : 0.f;
                float v0 = f.x + bv, v1 = f.y + bv;
                if (ACT == 1) { v0 = tanhf(v0); v1 = tanhf(v1); }
                C[(size_t)m0 * ldc + n]       = v0;
                C[(size_t)(m0 + 1) * ldc + n] = v1;
            }
        }
    }
}

// ---------------- encoder recurrence step (both directions per launch) --------
// grid = 512 blocks: [dir(2)][e-tile(16 of 16)][b-tile(16 of 8)], 128 threads.
__global__ void enc_step_kernel(const float* __restrict__ Whh_f,
                                const float* __restrict__ bhh_f,
                                const float* __restrict__ Whh_b,
                                const float* __restrict__ bhh_b,
                                int i)
{
    const int blk = blockIdx.x;
    const int dir = blk >> 8;
    const int et  = (blk >> 4) & 15;
    const int bt  = blk & 15;
    const int s   = dir ? (S_ - 1 - i) : i;

    const float* Whh = dir ? Whh_b : Whh_f;
    const float* bhh = dir ? bhh_b : bhh_f;
    const float* pre = dir ? g_pre_b : g_pre_f;
    const float* hin = g_h[dir][i & 1];
    float*       hout = g_h[dir][(i + 1) & 1];

    __shared__ float sh[8][E_];   // h for 8 batch elements
    const int tid = threadIdx.x;  // 128
    for (int idx = tid; idx < 8 * E_; idx += 128) {
        int bb = idx >> 8, e = idx & 255;
        sh[bb][e] = (i == 0) ? 0.f : hin[(bt * 8 + bb) * E_ + e];
    }
    __syncthreads();

    const int e  = et * 16 + (tid >> 3);
    const int bb = tid & 7;
    const float4* wrow = (const float4*)(Whh + (size_t)e * E_);
    const float4* hrow = (const float4*)&sh[bb][0];

    float a0 = 0.f, a1 = 0.f, a2 = 0.f, a3 = 0.f;
#pragma unroll 4
    for (int j = 0; j < 64; j += 4) {
        float4 w0 = wrow[j + 0], h0 = hrow[j + 0];
        float4 w1 = wrow[j + 1], h1 = hrow[j + 1];
        float4 w2 = wrow[j + 2], h2 = hrow[j + 2];
        float4 w3 = wrow[j + 3], h3 = hrow[j + 3];
        a0 += w0.x * h0.x + w0.y * h0.y + w0.z * h0.z + w0.w * h0.w;
        a1 += w1.x * h1.x + w1.y * h1.y + w1.z * h1.z + w1.w * h1.w;
        a2 += w2.x * h2.x + w2.y * h2.y + w2.z * h2.z + w2.w * h2.w;
        a3 += w3.x * h3.x + w3.y * h3.y + w3.z * h3.z + w3.w * h3.w;
    }
    const int b = bt * 8 + bb;
    float val = tanhf(pre[(size_t)s * B_ * E_ + b * E_ + e] + (a0 + a1) + (a2 + a3) + bhh[e]);
    hout[b * E_ + e] = val;
    g_enc_out[(size_t)s * B_ * (2 * E_) + b * (2 * E_) + dir * E_ + e] = val;
}

// ---------------- hcat = [h_f | h_b] (final states are in buf 0) --------------
__global__ void hcat_kernel()
{
    int b = blockIdx.x;
    int e = threadIdx.x;                       // 512 threads
    float v = (e < E_) ? g_h[0][0][b * E_ + e] : g_h[1][0][b * E_ + (e - E_)];
    g_hcat[b * 2 * E_ + e] = v;
}

// ---------------- fused attention: scores + softmax + context + embedding ----
__global__ void attn_kernel(const float* __restrict__ attn_v,
                            const float* __restrict__ emb_table,
                            const int*   __restrict__ trg,
                            int t)
{
    const int b   = blockIdx.x;          // 128 blocks
    const int tid = threadIdx.x;         // 256
    const int lane = tid & 31, w = tid >> 5;

    __shared__ float s_hw[D_];
    __shared__ float s_v[D_];
    __shared__ float s_sc[S_];
    __shared__ float s_m, s_sum;

    for (int d = tid; d < D_; d += 256) {
        s_hw[d] = g_hW[b * D_ + d];
        s_v[d]  = attn_v[d];
    }
    __syncthreads();

    // scores: 8 warps, 16 sequence positions each
    for (int s = w; s < S_; s += 8) {
        const float* ep = g_enc_part + ((size_t)s * B_ + b) * D_;
        float acc = 0.f;
        for (int d = lane; d < D_; d += 32)
            acc += tanhf(s_hw[d] + ep[d]) * s_v[d];
#pragma unroll
        for (int o = 16; o; o >>= 1) acc += __shfl_xor_sync(0xffffffffu, acc, o);
        if (lane == 0) s_sc[s] = acc;
    }
    __syncthreads();

    // softmax over S=128 (warp 0)
    if (tid < 32) {
        float m = -1e30f;
        for (int s = tid; s < S_; s += 32) m = fmaxf(m, s_sc[s]);
#pragma unroll
        for (int o = 16; o; o >>= 1) m = fmaxf(m, __shfl_xor_sync(0xffffffffu, m, o));
        float sum = 0.f;
        for (int s = tid; s < S_; s += 32) sum += expf(s_sc[s] - m);
#pragma unroll
        for (int o = 16; o; o >>= 1) sum += __shfl_xor_sync(0xffffffffu, sum, o);
        if (tid == 0) { s_m = m; s_sum = sum; }
    }
    __syncthreads();
    for (int s = tid; s < S_; s += 256) s_sc[s] = expf(s_sc[s] - s_m) / s_sum;
    __syncthreads();

    // weighted context over e (coalesced per s)
    for (int e = tid; e < 2 * E_; e += 256) {
        float acc = 0.f;
        const float* eo = g_enc_out + (size_t)b * (2 * E_) + e;
#pragma unroll 4
        for (int s = 0; s < S_; s++)
            acc += s_sc[s] * eo[(size_t)s * B_ * (2 * E_)];
        g_x[b * (EMB_ + 2 * E_) + EMB_ + e]      = acc;   // GRU input: [emb | weighted]
        g_pred_in[b * 1280 + D_ + e]             = acc;   // pred input slot
    }

    // embedding gather
    int tok = trg[b * T_ + t];
    for (int j = tid; j < EMB_; j += 256) {
        float v = emb_table[(size_t)tok * EMB_ + j];
        g_x[b * (EMB_ + 2 * E_) + j]             = v;
        g_pred_in[b * 1280 + D_ + 2 * E_ + j]    = v;
    }
}

// ---------------- GRU gates: h_new from gi, gh, h ----------------------------
__global__ void gru_gate_kernel()
{
    int idx = blockIdx.x * 256 + threadIdx.x;   // B*D
    int b = idx / D_, d = idx - b * D_;
    const float* gi = g_gi + (size_t)b * 3 * D_;
    const float* gh = g_gh + (size_t)b * 3 * D_;
    float r = 1.f / (1.f + expf(-(gi[d] + gh[d])));
    float z = 1.f / (1.f + expf(-(gi[D_ + d] + gh[D_ + d])));
    float n = tanhf(gi[2 * D_ + d] + r * gh[2 * D_ + d]);
    float h = g_hidden[idx];
    float hn = (1.f - z) * n + z * h;
    g_hidden[idx] = hn;
    g_pred_in[b * 1280 + d] = hn;
}

// ---------------- row softmax over V and write to output ---------------------
__global__ void softmax_out_kernel(float* __restrict__ out, int t)
{
    const int b = blockIdx.x;          // 128 blocks
    const int tid = threadIdx.x;       // 256
    const float* p = g_pred + (size_t)b * V_;
    __shared__ float red[8];
    const int lane = tid & 31, w = tid >> 5;

    float m = -1e30f;
    for (int v = tid; v < V_; v += 256) m = fmaxf(m, p[v]);
#pragma unroll
    for (int o = 16; o; o >>= 1) m = fmaxf(m, __shfl_xor_sync(0xffffffffu, m, o));
    if (lane == 0) red[w] = m;
    __syncthreads();
    if (tid < 8) {
        float v = red[tid];
#pragma unroll
        for (int o = 4; o; o >>= 1) v = fmaxf(v, __shfl_xor_sync(0xffu, v, o));
        if (tid == 0) red[0] = v;
    }
    __syncthreads();
    m = red[0];
    __syncthreads();

    float sum = 0.f;
    for (int v = tid; v < V_; v += 256) sum += expf(p[v] - m);
#pragma unroll
    for (int o = 16; o; o >>= 1) sum += __shfl_xor_sync(0xffffffffu, sum, o);
    if (lane == 0) red[w] = sum;
    __syncthreads();
    if (tid < 8) {
        float v = red[tid];
#pragma unroll
        for (int o = 4; o; o >>= 1) v += __shfl_xor_sync(0xffu, v, o);
        if (tid == 0) red[0] = v;
    }
    __syncthreads();
    float inv = 1.f / red[0];

    float* o = out + ((size_t)b * T_ + t) * V_;
    for (int v = tid; v < V_; v += 256) o[v] = expf(p[v] - m) * inv;
}

// ---------------- driver ------------------------------------------------------
extern "C" void kernel_launch(void* const* d_in, const int* in_sizes, int n_in,
                              void* d_out, int out_size)
{
    const float* src       = (const float*)d_in[0];
    const int*   trg       = (const int*)  d_in[1];
    const float* enc_Wih_f = (const float*)d_in[2];
    const float* enc_Whh_f = (const float*)d_in[3];
    const float* enc_bih_f = (const float*)d_in[4];
    const float* enc_bhh_f = (const float*)d_in[5];
    const float* enc_Wih_b = (const float*)d_in[6];
    const float* enc_Whh_b = (const float*)d_in[7];
    const float* enc_bih_b = (const float*)d_in[8];
    const float* enc_bhh_b = (const float*)d_in[9];
    const float* enc_fcW   = (const float*)d_in[10];
    const float* enc_fcb   = (const float*)d_in[11];
    const float* attn_W    = (const float*)d_in[12];
    const float* attn_b    = (const float*)d_in[13];
    const float* attn_v    = (const float*)d_in[14];
    const float* emb_table = (const float*)d_in[15];
    const float* gru_Wih   = (const float*)d_in[16];
    const float* gru_Whh   = (const float*)d_in[17];
    const float* gru_bih   = (const float*)d_in[18];
    const float* gru_bhh   = (const float*)d_in[19];
    const float* out_W     = (const float*)d_in[20];
    const float* out_b     = (const float*)d_in[21];
    float* out = (float*)d_out;

    float* pre_f;    cudaGetSymbolAddress((void**)&pre_f,    g_pre_f);
    float* pre_b;    cudaGetSymbolAddress((void**)&pre_b,    g_pre_b);
    float* enc_out;  cudaGetSymbolAddress((void**)&enc_out,  g_enc_out);
    float* enc_part; cudaGetSymbolAddress((void**)&enc_part, g_enc_part);
    float* hcat;     cudaGetSymbolAddress((void**)&hcat,     g_hcat);
    float* hidden;   cudaGetSymbolAddress((void**)&hidden,   g_hidden);
    float* hW;       cudaGetSymbolAddress((void**)&hW,       g_hW);
    float* xbuf;     cudaGetSymbolAddress((void**)&xbuf,     g_x);
    float* pred_in;  cudaGetSymbolAddress((void**)&pred_in,  g_pred_in);
    float* gi;       cudaGetSymbolAddress((void**)&gi,       g_gi);
    float* gh;       cudaGetSymbolAddress((void**)&gh,       g_gh);
    float* pred;     cudaGetSymbolAddress((void**)&pred,     g_pred);

    // 1) input projections: pre = src @ Wih^T + bih   (M=16384, N=256, K=256)
    {
        dim3 grid(E_ / 64, (S_ * B_) / 128);
        gemm_tn<128, 64, 16, 8, 4, 0><<<grid, 256>>>(src, C_, enc_Wih_f, C_, enc_bih_f,
                                                     pre_f, E_, S_ * B_, E_, C_);
        gemm_tn<128, 64, 16, 8, 4, 0><<<grid, 256>>>(src, C_, enc_Wih_b, C_, enc_bih_b,
                                                     pre_b, E_, S_ * B_, E_, C_);
    }

    // 2) encoder recurrence (fwd + bwd per launch)
    for (int i = 0; i < S_; i++)
        enc_step_kernel<<<512, 128>>>(enc_Whh_f, enc_bhh_f, enc_Whh_b, enc_bhh_b, i);

    // 3) hidden = tanh([h_f|h_b] @ fcW^T + fcb)   (M=128, N=512, K=512)
    hcat_kernel<<<B_, 2 * E_>>>();
    {
        dim3 grid(D_ / 32, B_ / 32);
        gemm_tn<32, 32, 16, 2, 2, 1><<<grid, 256>>>(hcat, 2 * E_, enc_fcW, 2 * E_, enc_fcb,
                                                    hidden, D_, B_, D_, 2 * E_);
    }

    // 4) enc_part = enc_out @ W_e^T + attn_b   (M=16384, N=512, K=512)
    {
        dim3 grid(D_ / 64, (S_ * B_) / 128);
        gemm_tn<128, 64, 16, 8, 4, 0><<<grid, 256>>>(enc_out, 2 * E_,
                                                     attn_W + D_, D_ + 2 * E_, attn_b,
                                                     enc_part, D_, S_ * B_, D_, 2 * E_);
    }

    // 5) decoder loop
    for (int t = 0; t < T_; t++) {
        // hW = h @ W_h^T   (M=128, N=512, K=512)
        {
            dim3 grid(D_ / 32, B_ / 32);
            gemm_tn<32, 32, 16, 2, 2, 0><<<grid, 256>>>(hidden, D_,
                                                        attn_W, D_ + 2 * E_, (const float*)nullptr,
                                                        hW, D_, B_, D_, D_);
        }
        // attention + context + embedding
        attn_kernel<<<B_, 256>>>(attn_v, emb_table, trg, t);
        // GRU gates
        {
            dim3 grid(3 * D_ / 32, B_ / 32);
            gemm_tn<32, 32, 16, 2, 2, 0><<<grid, 256>>>(xbuf, EMB_ + 2 * E_,
                                                        gru_Wih, EMB_ + 2 * E_, gru_bih,
                                                        gi, 3 * D_, B_, 3 * D_, EMB_ + 2 * E_);
            gemm_tn<32, 32, 16, 2, 2, 0><<<grid, 256>>>(hidden, D_,
                                                        gru_Whh, D_, gru_bhh,
                                                        gh, 3 * D_, B_, 3 * D_, D_);
        }
        gru_gate_kernel<<<(B_ * D_) / 256, 256>>>();
        // output projection (M=128, N=10000, K=1280)
        {
            dim3 grid((V_ + 63) / 64, B_ / 128);
            gemm_tn<128, 64, 16, 8, 4, 0><<<grid, 256>>>(pred_in, 1280,
                                                         out_W, 1280, out_b,
                                                         pred, V_, B_, V_, 1280);
        }
        softmax_out_kernel<<<B_, 256>>>(out, t);
    }
}

// round 5
// speedup vs baseline: 1.2409x; 1.2409x over previous
#include <cuda_runtime.h>
#include <math.h>

#define S_   128
#define B_   128
#define C_   256
#define E_   256
#define D_   512
#define EMB_ 256
#define V_   10000
#define T_   32

// ---------------- scratch (static device memory; no allocation at runtime) ----
__device__ float g_pre_f[S_*B_*E_];
__device__ float g_pre_b[S_*B_*E_];
__device__ float g_WhhT[2][E_*E_];                  // [dir][k*E+e] transposed weights
__device__ float g_enc_out[(size_t)S_*B_*2*E_];     // [s][b][0:256]=fwd, [256:512]=bwd
__device__ float g_enc_part[(size_t)S_*B_*D_];
__device__ float g_hcat[B_*2*E_];
__device__ float g_hidden[B_*D_];
__device__ float g_hW[B_*D_];
__device__ float g_x[B_*(EMB_+2*E_)];               // [emb | weighted], K=768
__device__ float g_pred_in[B_*(D_+2*E_+EMB_)];      // [h_new | weighted | emb], K=1280
__device__ float g_gi[B_*3*D_];
__device__ float g_gh[B_*3*D_];
__device__ float g_pred[B_*V_];

// packed fp32x2 FMA (sm_100a+): d = a*b + c elementwise on 2 packed floats
__device__ __forceinline__ unsigned long long ffma2(unsigned long long a,
                                                    unsigned long long b,
                                                    unsigned long long c)
{
    unsigned long long d;
    asm("fma.rn.f32x2 %0, %1, %2, %3;" : "=l"(d) : "l"(a), "l"(b), "l"(c));
    return d;
}

// ---------------- generic TN GEMM: C[M,N] = act(A[M,K] @ B[N,K]^T + bias[N]) --
// 256 threads as 16x16; thread tile TM x TN (TM even); BM=16*TM, BN=16*TN.
// Double-buffered smem: next tile's LDGs issue before compute, STS after.
template<int BM, int BN, int BK, int TM, int TN, int ACT>
__global__ void gemm_tn(const float* __restrict__ A, int lda,
                        const float* __restrict__ Bm, int ldb,
                        const float* __restrict__ bias,
                        float* __restrict__ C, int ldc,
                        int M, int N, int K)
{
    __shared__ float As[2][BK][BM + 4];
    __shared__ float Bs[2][BK][BN + 4];
    const int bm = blockIdx.y * BM;
    const int bn = blockIdx.x * BN;
    const int tid = threadIdx.x;
    const int tx = tid & 15, ty = tid >> 4;
    constexpr int MP = TM / 2;
    constexpr int NA = (BM * BK) / 256;
    constexpr int NB = (BN * BK) / 256;

    unsigned long long acc[MP][TN];
#pragma unroll
    for (int i = 0; i < MP; i++)
#pragma unroll
        for (int j = 0; j < TN; j++) acc[i][j] = 0ull;

    float ra[NA], rb[NB];

    // prologue: load k-tile 0
#pragma unroll
    for (int i = 0; i < NA; i++) {
        int id = tid + i * 256;
        ra[i] = A[(size_t)(bm + id / BK) * lda + (id % BK)];
    }
#pragma unroll
    for (int i = 0; i < NB; i++) {
        int id = tid + i * 256;
        int n = bn + id / BK;
        rb[i] = (n < N) ? Bm[(size_t)n * ldb + (id % BK)] : 0.f;
    }
#pragma unroll
    for (int i = 0; i < NA; i++) {
        int id = tid + i * 256;
        As[0][id % BK][id / BK] = ra[i];
    }
#pragma unroll
    for (int i = 0; i < NB; i++) {
        int id = tid + i * 256;
        Bs[0][id % BK][id / BK] = rb[i];
    }
    __syncthreads();

    const int nk = K / BK;
    for (int kt = 0; kt < nk; kt++) {
        const int buf = kt & 1;

        if (kt + 1 < nk) {
            const int k0 = (kt + 1) * BK;
#pragma unroll
            for (int i = 0; i < NA; i++) {
                int id = tid + i * 256;
                ra[i] = A[(size_t)(bm + id / BK) * lda + k0 + (id % BK)];
            }
#pragma unroll
            for (int i = 0; i < NB; i++) {
                int id = tid + i * 256;
                int n = bn + id / BK;
                rb[i] = (n < N) ? Bm[(size_t)n * ldb + k0 + (id % BK)] : 0.f;
            }
        }

#pragma unroll
        for (int k = 0; k < BK; k++) {
            unsigned long long a2[MP], b2[TN];
#pragma unroll
            for (int i = 0; i < MP; i++)
                a2[i] = *(const unsigned long long*)&As[buf][k][ty * TM + 2 * i];
#pragma unroll
            for (int j = 0; j < TN; j++) {
                float bv = Bs[buf][k][tx * TN + j];
                float2 bb = make_float2(bv, bv);
                b2[j] = *(unsigned long long*)&bb;
            }
#pragma unroll
            for (int i = 0; i < MP; i++)
#pragma unroll
                for (int j = 0; j < TN; j++)
                    acc[i][j] = ffma2(a2[i], b2[j], acc[i][j]);
        }

        if (kt + 1 < nk) {
            const int nb = buf ^ 1;
#pragma unroll
            for (int i = 0; i < NA; i++) {
                int id = tid + i * 256;
                As[nb][id % BK][id / BK] = ra[i];
            }
#pragma unroll
            for (int i = 0; i < NB; i++) {
                int id = tid + i * 256;
                Bs[nb][id % BK][id / BK] = rb[i];
            }
            __syncthreads();
        }
    }

#pragma unroll
    for (int i = 0; i < MP; i++) {
        int m0 = bm + ty * TM + 2 * i;
#pragma unroll
        for (int j = 0; j < TN; j++) {
            int n = bn + tx * TN + j;
            if (n < N) {
                float2 f = *(float2*)&acc[i][j];
                float bv = bias ? bias[n] : 0.f;
                float v0 = f.x + bv, v1 = f.y + bv;
                if (ACT == 1) { v0 = tanhf(v0); v1 = tanhf(v1); }
                C[(size_t)m0 * ldc + n]       = v0;
                C[(size_t)(m0 + 1) * ldc + n] = v1;
            }
        }
    }
}

// ---------------- weight transpose: WhhT[dir][k][e] = Whh[e][k] ---------------
__global__ void transpose_whh_kernel(const float* __restrict__ Whh_f,
                                     const float* __restrict__ Whh_b)
{
    const int dir = blockIdx.x;
    const int k   = blockIdx.y;            // 256 blocks
    const int e   = threadIdx.x;           // 256 threads
    const float* W = dir ? Whh_b : Whh_f;
    g_WhhT[dir][k * E_ + e] = W[e * E_ + k];
}

// ---------------- persistent encoder scan (whole 128-step recurrence) --------
// grid = 32 blocks: [dir(2)][b-tile(16 of 8)], 256 threads (thread = one e).
__global__ void enc_scan_kernel(const float* __restrict__ bhh_f,
                                const float* __restrict__ bhh_b)
{
    const int dir = blockIdx.x >> 4;
    const int bt  = blockIdx.x & 15;
    const int tid = threadIdx.x;           // e = tid
    const int b0  = bt * 8;

    const float* pre  = dir ? g_pre_b : g_pre_f;
    const float* wcol = g_WhhT[dir] + tid;           // WhhT[k*256+e], stride E_
    const float  bias = (dir ? bhh_b : bhh_f)[tid];

    __shared__ float hbuf[2][E_][8];                 // [buf][k][b] (16 KB)

    // init h = 0
#pragma unroll
    for (int p = 0; p < 8; p++) hbuf[0][tid][p] = 0.f;
    __syncthreads();

    for (int i = 0; i < S_; i++) {
        const int cur = i & 1, nxt = cur ^ 1;
        const int s = dir ? (S_ - 1 - i) : i;

        unsigned long long acc[4] = {0ull, 0ull, 0ull, 0ull};
#pragma unroll 8
        for (int k = 0; k < E_; k++) {
            float w = wcol[k * E_];
            float2 wp = make_float2(w, w);
            unsigned long long w2 = *(unsigned long long*)&wp;
            const unsigned long long* hk = (const unsigned long long*)&hbuf[cur][k][0];
#pragma unroll
            for (int p = 0; p < 4; p++)
                acc[p] = ffma2(w2, hk[p], acc[p]);
        }

        const float* prow = pre + (size_t)s * B_ * E_ + (size_t)b0 * E_ + tid;
        float* erow = g_enc_out + (size_t)s * B_ * (2 * E_) + (size_t)b0 * (2 * E_) + dir * E_ + tid;
#pragma unroll
        for (int p = 0; p < 4; p++) {
            float2 f = *(float2*)&acc[p];
            float v0 = tanhf(f.x + prow[(2 * p) * E_] + bias);
            float v1 = tanhf(f.y + prow[(2 * p + 1) * E_] + bias);
            hbuf[nxt][tid][2 * p]     = v0;
            hbuf[nxt][tid][2 * p + 1] = v1;
            erow[(2 * p) * (2 * E_)]     = v0;
            erow[(2 * p + 1) * (2 * E_)] = v1;
        }
        __syncthreads();
    }
}

// ---------------- hcat = [h_f | h_b] read from enc_out -----------------------
// h_f final = enc_out[S-1][b][0:256]; h_b final = enc_out[0][b][256:512]
__global__ void hcat_kernel()
{
    int b = blockIdx.x;
    int e = threadIdx.x;                       // 512 threads
    float v;
    if (e < E_)
        v = g_enc_out[(size_t)(S_ - 1) * B_ * (2 * E_) + b * (2 * E_) + e];
    else
        v = g_enc_out[(size_t)b * (2 * E_) + e];   // s=0, bwd half (e already >= 256)
    g_hcat[b * 2 * E_ + e] = v;
}

// ---------------- fused attention: scores + softmax + context + embedding ----
__global__ void attn_kernel(const float* __restrict__ attn_v,
                            const float* __restrict__ emb_table,
                            const int*   __restrict__ trg,
                            int t)
{
    const int b   = blockIdx.x;          // 128 blocks
    const int tid = threadIdx.x;         // 256
    const int lane = tid & 31, w = tid >> 5;

    __shared__ float s_hw[D_];
    __shared__ float s_v[D_];
    __shared__ float s_sc[S_];
    __shared__ float s_m, s_sum;

    for (int d = tid; d < D_; d += 256) {
        s_hw[d] = g_hW[b * D_ + d];
        s_v[d]  = attn_v[d];
    }
    __syncthreads();

    // scores: 8 warps, 16 sequence positions each
    for (int s = w; s < S_; s += 8) {
        const float* ep = g_enc_part + ((size_t)s * B_ + b) * D_;
        float acc = 0.f;
        for (int d = lane; d < D_; d += 32)
            acc += tanhf(s_hw[d] + ep[d]) * s_v[d];
#pragma unroll
        for (int o = 16; o; o >>= 1) acc += __shfl_xor_sync(0xffffffffu, acc, o);
        if (lane == 0) s_sc[s] = acc;
    }
    __syncthreads();

    // softmax over S=128 (warp 0)
    if (tid < 32) {
        float m = -1e30f;
        for (int s = tid; s < S_; s += 32) m = fmaxf(m, s_sc[s]);
#pragma unroll
        for (int o = 16; o; o >>= 1) m = fmaxf(m, __shfl_xor_sync(0xffffffffu, m, o));
        float sum = 0.f;
        for (int s = tid; s < S_; s += 32) sum += expf(s_sc[s] - m);
#pragma unroll
        for (int o = 16; o; o >>= 1) sum += __shfl_xor_sync(0xffffffffu, sum, o);
        if (tid == 0) { s_m = m; s_sum = sum; }
    }
    __syncthreads();
    for (int s = tid; s < S_; s += 256) s_sc[s] = expf(s_sc[s] - s_m) / s_sum;
    __syncthreads();

    // weighted context over e (coalesced per s)
    for (int e = tid; e < 2 * E_; e += 256) {
        float acc = 0.f;
        const float* eo = g_enc_out + (size_t)b * (2 * E_) + e;
#pragma unroll 4
        for (int s = 0; s < S_; s++)
            acc += s_sc[s] * eo[(size_t)s * B_ * (2 * E_)];
        g_x[b * (EMB_ + 2 * E_) + EMB_ + e]      = acc;   // GRU input: [emb | weighted]
        g_pred_in[b * 1280 + D_ + e]             = acc;   // pred input slot
    }

    // embedding gather
    int tok = trg[b * T_ + t];
    for (int j = tid; j < EMB_; j += 256) {
        float v = emb_table[(size_t)tok * EMB_ + j];
        g_x[b * (EMB_ + 2 * E_) + j]             = v;
        g_pred_in[b * 1280 + D_ + 2 * E_ + j]    = v;
    }
}

// ---------------- GRU gates: h_new from gi, gh, h ----------------------------
__global__ void gru_gate_kernel()
{
    int idx = blockIdx.x * 256 + threadIdx.x;   // B*D
    int b = idx / D_, d = idx - b * D_;
    const float* gi = g_gi + (size_t)b * 3 * D_;
    const float* gh = g_gh + (size_t)b * 3 * D_;
    float r = 1.f / (1.f + expf(-(gi[d] + gh[d])));
    float z = 1.f / (1.f + expf(-(gi[D_ + d] + gh[D_ + d])));
    float n = tanhf(gi[2 * D_ + d] + r * gh[2 * D_ + d]);
    float h = g_hidden[idx];
    float hn = (1.f - z) * n + z * h;
    g_hidden[idx] = hn;
    g_pred_in[b * 1280 + d] = hn;
}

// ---------------- row softmax over V and write to output ---------------------
__global__ void softmax_out_kernel(float* __restrict__ out, int t)
{
    const int b = blockIdx.x;          // 128 blocks
    const int tid = threadIdx.x;       // 256
    const float* p = g_pred + (size_t)b * V_;
    __shared__ float red[8];
    const int lane = tid & 31, w = tid >> 5;

    float m = -1e30f;
    for (int v = tid; v < V_; v += 256) m = fmaxf(m, p[v]);
#pragma unroll
    for (int o = 16; o; o >>= 1) m = fmaxf(m, __shfl_xor_sync(0xffffffffu, m, o));
    if (lane == 0) red[w] = m;
    __syncthreads();
    if (tid < 8) {
        float v = red[tid];
#pragma unroll
        for (int o = 4; o; o >>= 1) v = fmaxf(v, __shfl_xor_sync(0xffu, v, o));
        if (tid == 0) red[0] = v;
    }
    __syncthreads();
    m = red[0];
    __syncthreads();

    float sum = 0.f;
    for (int v = tid; v < V_; v += 256) sum += expf(p[v] - m);
#pragma unroll
    for (int o = 16; o; o >>= 1) sum += __shfl_xor_sync(0xffffffffu, sum, o);
    if (lane == 0) red[w] = sum;
    __syncthreads();
    if (tid < 8) {
        float v = red[tid];
#pragma unroll
        for (int o = 4; o; o >>= 1) v += __shfl_xor_sync(0xffu, v, o);
        if (tid == 0) red[0] = v;
    }
    __syncthreads();
    float inv = 1.f / red[0];

    float* o = out + ((size_t)b * T_ + t) * V_;
    for (int v = tid; v < V_; v += 256) o[v] = expf(p[v] - m) * inv;
}

// ---------------- driver ------------------------------------------------------
extern "C" void kernel_launch(void* const* d_in, const int* in_sizes, int n_in,
                              void* d_out, int out_size)
{
    const float* src       = (const float*)d_in[0];
    const int*   trg       = (const int*)  d_in[1];
    const float* enc_Wih_f = (const float*)d_in[2];
    const float* enc_Whh_f = (const float*)d_in[3];
    const float* enc_bih_f = (const float*)d_in[4];
    const float* enc_bhh_f = (const float*)d_in[5];
    const float* enc_Wih_b = (const float*)d_in[6];
    const float* enc_Whh_b = (const float*)d_in[7];
    const float* enc_bih_b = (const float*)d_in[8];
    const float* enc_bhh_b = (const float*)d_in[9];
    const float* enc_fcW   = (const float*)d_in[10];
    const float* enc_fcb   = (const float*)d_in[11];
    const float* attn_W    = (const float*)d_in[12];
    const float* attn_b    = (const float*)d_in[13];
    const float* attn_v    = (const float*)d_in[14];
    const float* emb_table = (const float*)d_in[15];
    const float* gru_Wih   = (const float*)d_in[16];
    const float* gru_Whh   = (const float*)d_in[17];
    const float* gru_bih   = (const float*)d_in[18];
    const float* gru_bhh   = (const float*)d_in[19];
    const float* out_W     = (const float*)d_in[20];
    const float* out_b     = (const float*)d_in[21];
    float* out = (float*)d_out;

    float* pre_f;    cudaGetSymbolAddress((void**)&pre_f,    g_pre_f);
    float* pre_b;    cudaGetSymbolAddress((void**)&pre_b,    g_pre_b);
    float* enc_out;  cudaGetSymbolAddress((void**)&enc_out,  g_enc_out);
    float* enc_part; cudaGetSymbolAddress((void**)&enc_part, g_enc_part);
    float* hcat;     cudaGetSymbolAddress((void**)&hcat,     g_hcat);
    float* hidden;   cudaGetSymbolAddress((void**)&hidden,   g_hidden);
    float* hW;       cudaGetSymbolAddress((void**)&hW,       g_hW);
    float* xbuf;     cudaGetSymbolAddress((void**)&xbuf,     g_x);
    float* pred_in;  cudaGetSymbolAddress((void**)&pred_in,  g_pred_in);
    float* gi;       cudaGetSymbolAddress((void**)&gi,       g_gi);
    float* gh;       cudaGetSymbolAddress((void**)&gh,       g_gh);
    float* pred;     cudaGetSymbolAddress((void**)&pred,     g_pred);

    // 0) transpose recurrence weights (k-major for coalesced scan loads)
    {
        dim3 grid(2, E_);
        transpose_whh_kernel<<<grid, E_>>>(enc_Whh_f, enc_Whh_b);
    }

    // 1) input projections: pre = src @ Wih^T + bih   (M=16384, N=256, K=256)
    {
        dim3 grid(E_ / 64, (S_ * B_) / 128);
        gemm_tn<128, 64, 16, 8, 4, 0><<<grid, 256>>>(src, C_, enc_Wih_f, C_, enc_bih_f,
                                                     pre_f, E_, S_ * B_, E_, C_);
        gemm_tn<128, 64, 16, 8, 4, 0><<<grid, 256>>>(src, C_, enc_Wih_b, C_, enc_bih_b,
                                                     pre_b, E_, S_ * B_, E_, C_);
    }

    // 2) encoder recurrence: single persistent kernel, 128 steps internal
    enc_scan_kernel<<<32, 256>>>(enc_bhh_f, enc_bhh_b);

    // 3) hidden = tanh([h_f|h_b] @ fcW^T + fcb)   (M=128, N=512, K=512)
    hcat_kernel<<<B_, 2 * E_>>>();
    {
        dim3 grid(D_ / 32, B_ / 32);
        gemm_tn<32, 32, 16, 2, 2, 1><<<grid, 256>>>(hcat, 2 * E_, enc_fcW, 2 * E_, enc_fcb,
                                                    hidden, D_, B_, D_, 2 * E_);
    }

    // 4) enc_part = enc_out @ W_e^T + attn_b   (M=16384, N=512, K=512)
    {
        dim3 grid(D_ / 64, (S_ * B_) / 128);
        gemm_tn<128, 64, 16, 8, 4, 0><<<grid, 256>>>(enc_out, 2 * E_,
                                                     attn_W + D_, D_ + 2 * E_, attn_b,
                                                     enc_part, D_, S_ * B_, D_, 2 * E_);
    }

    // 5) decoder loop
    for (int t = 0; t < T_; t++) {
        // hW = h @ W_h^T   (M=128, N=512, K=512)
        {
            dim3 grid(D_ / 32, B_ / 32);
            gemm_tn<32, 32, 16, 2, 2, 0><<<grid, 256>>>(hidden, D_,
                                                        attn_W, D_ + 2 * E_, (const float*)nullptr,
                                                        hW, D_, B_, D_, D_);
        }
        // attention + context + embedding
        attn_kernel<<<B_, 256>>>(attn_v, emb_table, trg, t);
        // GRU gates
        {
            dim3 grid(3 * D_ / 32, B_ / 32);
            gemm_tn<32, 32, 16, 2, 2, 0><<<grid, 256>>>(xbuf, EMB_ + 2 * E_,
                                                        gru_Wih, EMB_ + 2 * E_, gru_bih,
                                                        gi, 3 * D_, B_, 3 * D_, EMB_ + 2 * E_);
            gemm_tn<32, 32, 16, 2, 2, 0><<<grid, 256>>>(hidden, D_,
                                                        gru_Whh, D_, gru_bhh,
                                                        gh, 3 * D_, B_, 3 * D_, D_);
        }
        gru_gate_kernel<<<(B_ * D_) / 256, 256>>>();
        // output projection (M=128, N=10000, K=1280)
        {
            dim3 grid((V_ + 63) / 64, B_ / 128);
            gemm_tn<128, 64, 16, 8, 4, 0><<<grid, 256>>>(pred_in, 1280,
                                                         out_W, 1280, out_b,
                                                         pred, V_, B_, V_, 1280);
        }
        softmax_out_kernel<<<B_, 256>>>(out, t);
    }
}